// round 15
// baseline (speedup 1.0000x reference)
#include <cuda_runtime.h>
#include <cuda_fp16.h>
#include <stdint.h>

// ---------------------------------------------------------------------------
// TT-linear fused kernel, v15 = v11 (best, 226us) with the epilogue rebuilt:
// stage C stores f16 accumulators straight to a separate Yh buffer via
// stmatrix.x4.trans (no barrier between C and the transpose store), then one
// sync and a coalesced fp32 bias+store. 4 barriers per row (was 5).
// One aliased 64KB T2/T1 buffer + 8.96KB Yh. 2 CTAs/SM.
// ---------------------------------------------------------------------------

#define B_YH   65536
#define YHSTR  280
#define SMEM_BYTES (65536 + 16 * YHSTR * 2 + 1024)   // 75520

// fragment-ordered core matrices (fp16), layouts as v10/v11 (passing):
__device__ __half g_M1f[8 * 8 * 32 * 8];   // 32KB
__device__ __half g_M2f[16 * 32 * 4];      // 4KB
__device__ __half g_M0f[8 * 32 * 8];       // 4KB

__global__ void tt_prep_cores(const float* __restrict__ c0,
                              const float* __restrict__ c1,
                              const float* __restrict__ c2) {
    int t = blockIdx.x * blockDim.x + threadIdx.x;
    int lane = t & 31, g = (lane >> 2), c = lane & 3;
    if (t < 2048) {                       // M1f: (kk, nt, lane)
        int kk = t >> 8, nt = (t >> 5) & 7;
        #pragma unroll
        for (int r = 0; r < 4; r++)
            #pragma unroll
            for (int h = 0; h < 2; h++) {
                int n = 16 * nt + g + 8 * (r & 1);
                int k = 16 * kk + 8 * (r >> 1) + 2 * c + h;
                int o1 = n >> 3, r1 = n & 7, i1 = k >> 3, r2 = k & 7;
                g_M1f[t * 8 + r * 2 + h] =
                    __float2half(c1[((r1 * 16 + o1) * 16 + i1) * 8 + r2]);
            }
    }
    if (t < 512) {                        // M2f: (nt8, lane)
        int nt8 = t >> 5;
        #pragma unroll
        for (int r = 0; r < 2; r++)
            #pragma unroll
            for (int h = 0; h < 2; h++) {
                int n = 8 * nt8 + g;
                int k = 8 * r + 2 * c + h;            // logical mma-k
                int o2 = n >> 3, r2 = n & 7;
                int cc = (k >> 1) & 3, d = k & 1, e = k >> 3;
                int i2 = 4 * cc + 2 * e + d;          // sigma(k)
                g_M2f[t * 4 + r * 2 + h] =
                    __float2half(c2[(r2 * 16 + o2) * 16 + i2]);
            }
    }
    if (t < 256) {                        // M0f: (ks=0..7, lane)
        int ks = t >> 5;
        #pragma unroll
        for (int r = 0; r < 4; r++)
            #pragma unroll
            for (int h = 0; h < 2; h++) {
                int n = g + 8 * (r & 1);              // o0
                int k = 16 * ks + 8 * (r >> 1) + 2 * c + h;
                int i0 = k >> 3, r1 = k & 7;
                g_M0f[t * 8 + r * 2 + h] =
                    __float2half(c0[(n * 16 + i0) * 8 + r1]);
            }
    }
}

__device__ __forceinline__ void mma16816h(uint32_t* d, const uint32_t* a,
                                          uint32_t b0, uint32_t b1) {
    asm volatile(
        "mma.sync.aligned.m16n8k16.row.col.f16.f16.f16.f16 "
        "{%0,%1}, {%2,%3,%4,%5}, {%6,%7}, {%0,%1};\n"
        : "+r"(d[0]), "+r"(d[1])
        : "r"(a[0]), "r"(a[1]), "r"(a[2]), "r"(a[3]), "r"(b0), "r"(b1));
}

__device__ __forceinline__ void ldsm4(uint32_t* r, uint32_t addr) {
    asm volatile(
        "ldmatrix.sync.aligned.m8n8.x4.shared.b16 {%0,%1,%2,%3}, [%4];\n"
        : "=r"(r[0]), "=r"(r[1]), "=r"(r[2]), "=r"(r[3]) : "r"(addr));
}

__device__ __forceinline__ void stsm2(uint32_t addr, uint32_t r0, uint32_t r1) {
    asm volatile(
        "stmatrix.sync.aligned.m8n8.x2.shared.b16 [%0], {%1,%2};\n"
        :: "r"(addr), "r"(r0), "r"(r1) : "memory");
}

__device__ __forceinline__ void stsm4(uint32_t addr, uint32_t r0, uint32_t r1,
                                      uint32_t r2, uint32_t r3) {
    asm volatile(
        "stmatrix.sync.aligned.m8n8.x4.shared.b16 [%0], {%1,%2,%3,%4};\n"
        :: "r"(addr), "r"(r0), "r"(r1), "r"(r2), "r"(r3) : "memory");
}

__device__ __forceinline__ void stsm4t(uint32_t addr, uint32_t r0, uint32_t r1,
                                       uint32_t r2, uint32_t r3) {
    asm volatile(
        "stmatrix.sync.aligned.m8n8.x4.trans.shared.b16 [%0], {%1,%2,%3,%4};\n"
        :: "r"(addr), "r"(r0), "r"(r1), "r"(r2), "r"(r3) : "memory");
}

__device__ __forceinline__ uint32_t packh2(float lo, float hi) {
    __half2 h = __floats2half2_rn(lo, hi);
    return *(uint32_t*)&h;
}

__global__ void __launch_bounds__(256, 2)
tt_linear_kernel(const float* __restrict__ x, const float* __restrict__ bias,
                 float* __restrict__ y) {
    extern __shared__ __half smem[];
    uint32_t sbase;
    asm("{ .reg .u64 t; cvta.to.shared.u64 t, %1; cvt.u32.u64 %0, t; }"
        : "=r"(sbase) : "l"(smem));
    const uint32_t abase = (sbase + 1023) & ~1023u;
    char* scp = (char*)smem + (abase - sbase);

    const int b    = blockIdx.x;
    const int tid  = threadIdx.x;
    const int w    = tid >> 5;
    const int lane = tid & 31;
    const int g = lane >> 2, c = lane & 3;
    const int lsel = lane & 15;
    const int hi   = lane >> 4;
    const int msel = lane >> 3;            // stmatrix matrix id
    const int mrow = lane & 7;             // stmatrix row-in-matrix

    const int mw = w & 3;                  // stage B m-warp
    const int nw = w >> 2;                 // stage B n-warp

    const float* xr = x + (size_t)b * 4096;
    const uint4* M1v = (const uint4*)g_M1f;
    const uint2* M2v = (const uint2*)g_M2f;
    const uint4* M0v = (const uint4*)g_M0f;

    // =====================================================================
    // stage A: x (256x16 logical) @ M2^T -> BUF as T2.
    // warp w owns i0 in {2w, 2w+1} -> x loaded exactly once.
    // T2: row = i0*16 + o2 (256 rows x 256B), chunk = i1, XOR ^(row&7).
    // =====================================================================
    {
        uint32_t a[2][4];
        #pragma unroll
        for (int mi = 0; mi < 2; mi++) {
            const int li0 = 2 * w + mi;
            const float* rp = xr + li0 * 256 + 16 * g + 4 * c;
            float4 f0 = *(const float4*)(rp);
            float4 f1 = *(const float4*)(rp + 128);
            a[mi][0] = packh2(f0.x, f0.y);
            a[mi][1] = packh2(f1.x, f1.y);
            a[mi][2] = packh2(f0.z, f0.w);
            a[mi][3] = packh2(f1.z, f1.w);
        }
        const int i1s = mrow + 8 * (msel & 1);        // stsm source row
        const int li0s = 2 * w + (msel >> 1);
        #pragma unroll
        for (int nt8 = 0; nt8 < 16; nt8++) {         // o2
            uint2 bf = M2v[nt8 * 32 + lane];
            uint32_t d[2][2];
            #pragma unroll
            for (int mi = 0; mi < 2; mi++) {
                d[mi][0] = 0u; d[mi][1] = 0u;
                mma16816h(d[mi], a[mi], bf.x, bf.y);
            }
            const uint32_t swo = ((uint32_t)(i1s ^ (nt8 & 7))) << 4;
            stsm4(abase + (uint32_t)(16 * li0s + nt8) * 256 + swo,
                  d[0][0], d[0][1], d[1][0], d[1][1]);
        }
    }
    __syncthreads();

    // =====================================================================
    // stage B: T2 (256x128) @ M1^T, single pass, f16 acc (64 regs).
    // warp grid 4M x 2N: per warp 4 mi (64 m-rows), 4 jj (64 n-cols).
    // =====================================================================
    uint32_t accb[4][8][2];
    #pragma unroll
    for (int mi = 0; mi < 4; mi++)
        #pragma unroll
        for (int s = 0; s < 8; s++) {
            accb[mi][s][0] = 0u; accb[mi][s][1] = 0u;
        }
    {
        uint32_t abm[4];
        #pragma unroll
        for (int mi = 0; mi < 4; mi++) {
            const int ar = 64 * mw + 16 * mi + lsel;
            abm[mi] = abase + (uint32_t)ar * 256 +
                      ((uint32_t)(hi ^ (ar & 7)) << 4);
        }
        #pragma unroll
        for (int kk = 0; kk < 8; kk++) {
            uint32_t a[4][4];
            #pragma unroll
            for (int mi = 0; mi < 4; mi++)
                ldsm4(a[mi], abm[mi] ^ ((uint32_t)(2 * kk) << 4));
            #pragma unroll
            for (int jj = 0; jj < 4; jj++) {
                const int nt = 4 * nw + jj;           // 16-wide n-tile
                uint4 bf = M1v[(kk * 8 + nt) * 32 + lane];
                #pragma unroll
                for (int mi = 0; mi < 4; mi++) {
                    mma16816h(accb[mi][2 * jj],     a[mi], bf.x, bf.z);
                    mma16816h(accb[mi][2 * jj + 1], a[mi], bf.y, bf.w);
                }
            }
        }
    }
    __syncthreads();   // all T2 reads done; BUF reusable as T1

    // scatter to T1 (aliased): row = 16*o1 + o2 (256 rows x 256B),
    // chunk = i0, XOR ^(o2&7).
    {
        const int o2v = mrow + 8 * (msel & 1);
        #pragma unroll
        for (int p = 0; p < 2; p++) {
            const int c16 = 4 * mw + 2 * p + (msel >> 1);   // i0
            const uint32_t swo = ((uint32_t)(c16 ^ mrow)) << 4;
            #pragma unroll
            for (int slot = 0; slot < 8; slot++) {
                const int o1 = 8 * nw + slot;
                stsm4(abase + (uint32_t)(16 * o1 + o2v) * 256 + swo,
                      accb[2 * p][slot][0],     accb[2 * p][slot][1],
                      accb[2 * p + 1][slot][0], accb[2 * p + 1][slot][1]);
            }
        }
    }
    __syncthreads();

    // =====================================================================
    // stage C: T1 (256x128) @ M0^T -> f16 accumulators, then straight to
    // Yh via stmatrix.x4.trans (no barrier: Yh disjoint from BUF).
    // =====================================================================
    uint32_t accc[2][2][2];
    #pragma unroll
    for (int mi = 0; mi < 2; mi++)
        #pragma unroll
        for (int nt = 0; nt < 2; nt++) {
            accc[mi][nt][0] = 0u; accc[mi][nt][1] = 0u;
        }
    #pragma unroll
    for (int ks = 0; ks < 8; ks++) {
        uint32_t a[2][4];
        #pragma unroll
        for (int mi = 0; mi < 2; mi++) {
            const int row = 16 * (w + 8 * mi) + lsel;
            ldsm4(a[mi], abase + (uint32_t)row * 256 +
                         ((uint32_t)((2 * ks + hi) ^ (lsel & 7)) << 4));
        }
        uint4 bf = M0v[ks * 32 + lane];
        #pragma unroll
        for (int mi = 0; mi < 2; mi++) {
            mma16816h(accc[mi][0], a[mi], bf.x, bf.z);
            mma16816h(accc[mi][1], a[mi], bf.y, bf.w);
        }
    }
    // transposed store: Yh[o0][row=(o1*16+o2)], stride YHSTR halves.
    // matrix m: rows o0 = mrow + 8*(msel>>1), cols row0 + 8*(msel&1).
    #pragma unroll
    for (int mi = 0; mi < 2; mi++) {
        const uint32_t addr = abase + B_YH +
            ((uint32_t)(mrow + 8 * (msel >> 1)) * YHSTR +
             (uint32_t)(16 * (w + 8 * mi) + 8 * (msel & 1))) * 2;
        stsm4t(addr, accc[mi][0][0], accc[mi][0][1],
                     accc[mi][1][0], accc[mi][1][1]);
    }
    __syncthreads();

    // ---- out: coalesced fp32 bias + store (16 floats per thread) ----
    float* yr = y + (size_t)b * 4096;
    {
        const int o0   = tid >> 4;
        const int colf = (tid & 15) * 16;
        const char* yp = scp + B_YH + ((uint32_t)o0 * YHSTR + colf) * 2;
        uint4 ha = *(const uint4*)(yp);
        uint4 hb = *(const uint4*)(yp + 16);
        const int i = o0 * 256 + colf;
        float4 b0 = *(const float4*)&bias[i];
        float4 b1 = *(const float4*)&bias[i + 4];
        float4 b2 = *(const float4*)&bias[i + 8];
        float4 b3 = *(const float4*)&bias[i + 12];
        float2 p0 = __half22float2(*(__half2*)&ha.x);
        float2 p1 = __half22float2(*(__half2*)&ha.y);
        float2 p2 = __half22float2(*(__half2*)&ha.z);
        float2 p3 = __half22float2(*(__half2*)&ha.w);
        float2 p4 = __half22float2(*(__half2*)&hb.x);
        float2 p5 = __half22float2(*(__half2*)&hb.y);
        float2 p6 = __half22float2(*(__half2*)&hb.z);
        float2 p7 = __half22float2(*(__half2*)&hb.w);
        float4 v0 = {p0.x + b0.x, p0.y + b0.y, p1.x + b0.z, p1.y + b0.w};
        float4 v1 = {p2.x + b1.x, p2.y + b1.y, p3.x + b1.z, p3.y + b1.w};
        float4 v2 = {p4.x + b2.x, p4.y + b2.y, p5.x + b2.z, p5.y + b2.w};
        float4 v3 = {p6.x + b3.x, p6.y + b3.y, p7.x + b3.z, p7.y + b3.w};
        *(float4*)&yr[i]      = v0;
        *(float4*)&yr[i + 4]  = v1;
        *(float4*)&yr[i + 8]  = v2;
        *(float4*)&yr[i + 12] = v3;
    }
}

extern "C" void kernel_launch(void* const* d_in, const int* in_sizes, int n_in,
                              void* d_out, int out_size) {
    const float* x    = (const float*)d_in[0];
    const float* c0   = (const float*)d_in[1];
    const float* c1   = (const float*)d_in[2];
    const float* c2   = (const float*)d_in[3];
    const float* bias = (const float*)d_in[4];
    float* y = (float*)d_out;

    cudaFuncSetAttribute(tt_linear_kernel,
                         cudaFuncAttributeMaxDynamicSharedMemorySize,
                         SMEM_BYTES);

    tt_prep_cores<<<4, 512>>>(c0, c1, c2);
    tt_linear_kernel<<<8192, 256, SMEM_BYTES>>>(x, bias, y);
}

// round 16
// speedup vs baseline: 1.6252x; 1.6252x over previous
#include <cuda_runtime.h>
#include <cuda_fp16.h>
#include <stdint.h>

// ---------------------------------------------------------------------------
// TT-linear fused kernel, v16 = v11 (best, 226us) processing 2 batch rows per
// CTA (grid 4096, ~14 waves instead of ~28) with one boundary sync per row.
// No cp.async, no stmatrix.trans, registers unchanged. 2 CTAs/SM.
// ---------------------------------------------------------------------------

#define SMEM_BYTES (65536 + 1024)
#define ROWS_PER_CTA 2

// fragment-ordered core matrices (fp16), layouts as v10/v11 (passing):
__device__ __half g_M1f[8 * 8 * 32 * 8];   // 32KB
__device__ __half g_M2f[16 * 32 * 4];      // 4KB
__device__ __half g_M0f[8 * 32 * 8];       // 4KB

__global__ void tt_prep_cores(const float* __restrict__ c0,
                              const float* __restrict__ c1,
                              const float* __restrict__ c2) {
    int t = blockIdx.x * blockDim.x + threadIdx.x;
    int lane = t & 31, g = (lane >> 2), c = lane & 3;
    if (t < 2048) {                       // M1f: (kk, nt, lane)
        int kk = t >> 8, nt = (t >> 5) & 7;
        #pragma unroll
        for (int r = 0; r < 4; r++)
            #pragma unroll
            for (int h = 0; h < 2; h++) {
                int n = 16 * nt + g + 8 * (r & 1);
                int k = 16 * kk + 8 * (r >> 1) + 2 * c + h;
                int o1 = n >> 3, r1 = n & 7, i1 = k >> 3, r2 = k & 7;
                g_M1f[t * 8 + r * 2 + h] =
                    __float2half(c1[((r1 * 16 + o1) * 16 + i1) * 8 + r2]);
            }
    }
    if (t < 512) {                        // M2f: (nt8, lane)
        int nt8 = t >> 5;
        #pragma unroll
        for (int r = 0; r < 2; r++)
            #pragma unroll
            for (int h = 0; h < 2; h++) {
                int n = 8 * nt8 + g;
                int k = 8 * r + 2 * c + h;            // logical mma-k
                int o2 = n >> 3, r2 = n & 7;
                int cc = (k >> 1) & 3, d = k & 1, e = k >> 3;
                int i2 = 4 * cc + 2 * e + d;          // sigma(k)
                g_M2f[t * 4 + r * 2 + h] =
                    __float2half(c2[(r2 * 16 + o2) * 16 + i2]);
            }
    }
    if (t < 256) {                        // M0f: (ks=0..7, lane)
        int ks = t >> 5;
        #pragma unroll
        for (int r = 0; r < 4; r++)
            #pragma unroll
            for (int h = 0; h < 2; h++) {
                int n = g + 8 * (r & 1);              // o0
                int k = 16 * ks + 8 * (r >> 1) + 2 * c + h;
                int i0 = k >> 3, r1 = k & 7;
                g_M0f[t * 8 + r * 2 + h] =
                    __float2half(c0[(n * 16 + i0) * 8 + r1]);
            }
    }
}

__device__ __forceinline__ void mma16816h(uint32_t* d, const uint32_t* a,
                                          uint32_t b0, uint32_t b1) {
    asm volatile(
        "mma.sync.aligned.m16n8k16.row.col.f16.f16.f16.f16 "
        "{%0,%1}, {%2,%3,%4,%5}, {%6,%7}, {%0,%1};\n"
        : "+r"(d[0]), "+r"(d[1])
        : "r"(a[0]), "r"(a[1]), "r"(a[2]), "r"(a[3]), "r"(b0), "r"(b1));
}

__device__ __forceinline__ void ldsm4(uint32_t* r, uint32_t addr) {
    asm volatile(
        "ldmatrix.sync.aligned.m8n8.x4.shared.b16 {%0,%1,%2,%3}, [%4];\n"
        : "=r"(r[0]), "=r"(r[1]), "=r"(r[2]), "=r"(r[3]) : "r"(addr));
}

__device__ __forceinline__ void stsm4(uint32_t addr, uint32_t r0, uint32_t r1,
                                      uint32_t r2, uint32_t r3) {
    asm volatile(
        "stmatrix.sync.aligned.m8n8.x4.shared.b16 [%0], {%1,%2,%3,%4};\n"
        :: "r"(addr), "r"(r0), "r"(r1), "r"(r2), "r"(r3) : "memory");
}

__device__ __forceinline__ uint32_t packh2(float lo, float hi) {
    __half2 h = __floats2half2_rn(lo, hi);
    return *(uint32_t*)&h;
}

__global__ void __launch_bounds__(256, 2)
tt_linear_kernel(const float* __restrict__ x, const float* __restrict__ bias,
                 float* __restrict__ y) {
    extern __shared__ __half smem[];
    uint32_t sbase;
    asm("{ .reg .u64 t; cvta.to.shared.u64 t, %1; cvt.u32.u64 %0, t; }"
        : "=r"(sbase) : "l"(smem));
    const uint32_t abase = (sbase + 1023) & ~1023u;
    char* scp = (char*)smem + (abase - sbase);
    float* Ysm = (float*)scp;             // aliases BUF at epilogue

    const int tid  = threadIdx.x;
    const int w    = tid >> 5;
    const int lane = tid & 31;
    const int g = lane >> 2, c = lane & 3;
    const int lsel = lane & 15;
    const int hi   = lane >> 4;
    const int msel = lane >> 3;            // stmatrix matrix id
    const int mrow = lane & 7;             // stmatrix row-in-matrix

    const int mw = w & 3;                  // stage B m-warp
    const int nw = w >> 2;                 // stage B n-warp

    const uint4* M1v = (const uint4*)g_M1f;
    const uint2* M2v = (const uint2*)g_M2f;
    const uint4* M0v = (const uint4*)g_M0f;

    #pragma unroll 1
    for (int r = 0; r < ROWS_PER_CTA; r++) {
        const size_t row = (size_t)blockIdx.x * ROWS_PER_CTA + r;
        const float* xr = x + row * 4096;
        float*       yr = y + row * 4096;

        // =================================================================
        // stage A: x (256x16 logical) @ M2^T -> BUF as T2.
        // warp w owns i0 in {2w, 2w+1} -> x loaded exactly once.
        // T2: row = i0*16 + o2 (256 rows x 256B), chunk = i1, XOR ^(row&7).
        // =================================================================
        {
            uint32_t a[2][4];
            #pragma unroll
            for (int mi = 0; mi < 2; mi++) {
                const int li0 = 2 * w + mi;
                const float* rp = xr + li0 * 256 + 16 * g + 4 * c;
                float4 f0 = *(const float4*)(rp);
                float4 f1 = *(const float4*)(rp + 128);
                a[mi][0] = packh2(f0.x, f0.y);
                a[mi][1] = packh2(f1.x, f1.y);
                a[mi][2] = packh2(f0.z, f0.w);
                a[mi][3] = packh2(f1.z, f1.w);
            }
            const int i1s = mrow + 8 * (msel & 1);    // stsm source row
            const int li0s = 2 * w + (msel >> 1);
            #pragma unroll
            for (int nt8 = 0; nt8 < 16; nt8++) {     // o2
                uint2 bf = M2v[nt8 * 32 + lane];
                uint32_t d[2][2];
                #pragma unroll
                for (int mi = 0; mi < 2; mi++) {
                    d[mi][0] = 0u; d[mi][1] = 0u;
                    mma16816h(d[mi], a[mi], bf.x, bf.y);
                }
                const uint32_t swo = ((uint32_t)(i1s ^ (nt8 & 7))) << 4;
                stsm4(abase + (uint32_t)(16 * li0s + nt8) * 256 + swo,
                      d[0][0], d[0][1], d[1][0], d[1][1]);
            }
        }
        __syncthreads();

        // =================================================================
        // stage B: T2 (256x128) @ M1^T, single pass, f16 acc (64 regs).
        // warp grid 4M x 2N: per warp 4 mi (64 m-rows), 4 jj (64 n-cols).
        // =================================================================
        uint32_t accb[4][8][2];
        #pragma unroll
        for (int mi = 0; mi < 4; mi++)
            #pragma unroll
            for (int s = 0; s < 8; s++) {
                accb[mi][s][0] = 0u; accb[mi][s][1] = 0u;
            }
        {
            uint32_t abm[4];
            #pragma unroll
            for (int mi = 0; mi < 4; mi++) {
                const int ar = 64 * mw + 16 * mi + lsel;
                abm[mi] = abase + (uint32_t)ar * 256 +
                          ((uint32_t)(hi ^ (ar & 7)) << 4);
            }
            #pragma unroll
            for (int kk = 0; kk < 8; kk++) {
                uint32_t a[4][4];
                #pragma unroll
                for (int mi = 0; mi < 4; mi++)
                    ldsm4(a[mi], abm[mi] ^ ((uint32_t)(2 * kk) << 4));
                #pragma unroll
                for (int jj = 0; jj < 4; jj++) {
                    const int nt = 4 * nw + jj;       // 16-wide n-tile
                    uint4 bf = M1v[(kk * 8 + nt) * 32 + lane];
                    #pragma unroll
                    for (int mi = 0; mi < 4; mi++) {
                        mma16816h(accb[mi][2 * jj],     a[mi], bf.x, bf.z);
                        mma16816h(accb[mi][2 * jj + 1], a[mi], bf.y, bf.w);
                    }
                }
            }
        }
        __syncthreads();   // all T2 reads done; BUF reusable as T1

        // scatter to T1 (aliased): row = 16*o1 + o2 (256 rows x 256B),
        // chunk = i0, XOR ^(o2&7).
        {
            const int o2v = mrow + 8 * (msel & 1);
            #pragma unroll
            for (int p = 0; p < 2; p++) {
                const int c16 = 4 * mw + 2 * p + (msel >> 1);   // i0
                const uint32_t swo = ((uint32_t)(c16 ^ mrow)) << 4;
                #pragma unroll
                for (int slot = 0; slot < 8; slot++) {
                    const int o1 = 8 * nw + slot;
                    stsm4(abase + (uint32_t)(16 * o1 + o2v) * 256 + swo,
                          accb[2 * p][slot][0],     accb[2 * p][slot][1],
                          accb[2 * p + 1][slot][0], accb[2 * p + 1][slot][1]);
                }
            }
        }
        __syncthreads();

        // =================================================================
        // stage C: T1 (256x128) @ M0^T -> f16 accumulators (8 regs)
        // =================================================================
        uint32_t accc[2][2][2];
        #pragma unroll
        for (int mi = 0; mi < 2; mi++)
            #pragma unroll
            for (int nt = 0; nt < 2; nt++) {
                accc[mi][nt][0] = 0u; accc[mi][nt][1] = 0u;
            }
        #pragma unroll
        for (int ks = 0; ks < 8; ks++) {
            uint32_t a[2][4];
            #pragma unroll
            for (int mi = 0; mi < 2; mi++) {
                const int rw = 16 * (w + 8 * mi) + lsel;
                ldsm4(a[mi], abase + (uint32_t)rw * 256 +
                             ((uint32_t)((2 * ks + hi) ^ (lsel & 7)) << 4));
            }
            uint4 bf = M0v[ks * 32 + lane];
            #pragma unroll
            for (int mi = 0; mi < 2; mi++) {
                mma16816h(accc[mi][0], a[mi], bf.x, bf.z);
                mma16816h(accc[mi][1], a[mi], bf.y, bf.w);
            }
        }
        __syncthreads();   // T1 reads done; BUF reusable as Ysm

        // ---- epilogue: transpose through Ysm (stride 260), float4 out ----
        #pragma unroll
        for (int mi = 0; mi < 2; mi++) {
            const int row0 = 16 * (w + 8 * mi) + g;   // o1*16+o2
            #pragma unroll
            for (int nt = 0; nt < 2; nt++) {
                const int col0 = 8 * nt + 2 * c;      // o0
                float2 v0 = __half22float2(*(__half2*)&accc[mi][nt][0]);
                float2 v1 = __half22float2(*(__half2*)&accc[mi][nt][1]);
                Ysm[(col0)     * 260 + row0]     = v0.x;
                Ysm[(col0 + 1) * 260 + row0]     = v0.y;
                Ysm[(col0)     * 260 + row0 + 8] = v1.x;
                Ysm[(col0 + 1) * 260 + row0 + 8] = v1.y;
            }
        }
        __syncthreads();

        #pragma unroll
        for (int it = 0; it < 4; it++) {
            const int i = 4 * (tid + 256 * it);       // i = o0*256 + row
            const int o0 = i >> 8, rr = i & 255;
            float4 v = *(const float4*)&Ysm[o0 * 260 + rr];
            float4 bb = *(const float4*)&bias[i];
            v.x += bb.x; v.y += bb.y; v.z += bb.z; v.w += bb.w;
            *(float4*)&yr[i] = v;
        }
        if (r + 1 < ROWS_PER_CTA)
            __syncthreads();   // Ysm reads done before next row's stage A
    }
}

extern "C" void kernel_launch(void* const* d_in, const int* in_sizes, int n_in,
                              void* d_out, int out_size) {
    const float* x    = (const float*)d_in[0];
    const float* c0   = (const float*)d_in[1];
    const float* c1   = (const float*)d_in[2];
    const float* c2   = (const float*)d_in[3];
    const float* bias = (const float*)d_in[4];
    float* y = (float*)d_out;

    cudaFuncSetAttribute(tt_linear_kernel,
                         cudaFuncAttributeMaxDynamicSharedMemorySize,
                         SMEM_BYTES);

    tt_prep_cores<<<4, 512>>>(c0, c1, c2);
    tt_linear_kernel<<<8192 / ROWS_PER_CTA, 256, SMEM_BYTES>>>(x, bias, y);
}

// round 17
// speedup vs baseline: 1.6860x; 1.0374x over previous
#include <cuda_runtime.h>
#include <cuda_fp16.h>
#include <stdint.h>

// ---------------------------------------------------------------------------
// TT-linear fused kernel, v17 = v11 (best, 226us) with Ysm moved to its own
// smem region (no alias with BUF) so the stage-C -> transpose barrier is
// removed: 4 barriers per row instead of 5. Register-neutral by design.
// One 64KB T2/T1 aliased buffer + 16.6KB Ysm. 2 CTAs/SM.
// ---------------------------------------------------------------------------

#define B_YS   65536
#define SMEM_BYTES (65536 + 16 * 260 * 4 + 1024)   // 83200

// fragment-ordered core matrices (fp16), layouts as v10/v11 (passing):
__device__ __half g_M1f[8 * 8 * 32 * 8];   // 32KB
__device__ __half g_M2f[16 * 32 * 4];      // 4KB
__device__ __half g_M0f[8 * 32 * 8];       // 4KB

__global__ void tt_prep_cores(const float* __restrict__ c0,
                              const float* __restrict__ c1,
                              const float* __restrict__ c2) {
    int t = blockIdx.x * blockDim.x + threadIdx.x;
    int lane = t & 31, g = (lane >> 2), c = lane & 3;
    if (t < 2048) {                       // M1f: (kk, nt, lane)
        int kk = t >> 8, nt = (t >> 5) & 7;
        #pragma unroll
        for (int r = 0; r < 4; r++)
            #pragma unroll
            for (int h = 0; h < 2; h++) {
                int n = 16 * nt + g + 8 * (r & 1);
                int k = 16 * kk + 8 * (r >> 1) + 2 * c + h;
                int o1 = n >> 3, r1 = n & 7, i1 = k >> 3, r2 = k & 7;
                g_M1f[t * 8 + r * 2 + h] =
                    __float2half(c1[((r1 * 16 + o1) * 16 + i1) * 8 + r2]);
            }
    }
    if (t < 512) {                        // M2f: (nt8, lane)
        int nt8 = t >> 5;
        #pragma unroll
        for (int r = 0; r < 2; r++)
            #pragma unroll
            for (int h = 0; h < 2; h++) {
                int n = 8 * nt8 + g;
                int k = 8 * r + 2 * c + h;            // logical mma-k
                int o2 = n >> 3, r2 = n & 7;
                int cc = (k >> 1) & 3, d = k & 1, e = k >> 3;
                int i2 = 4 * cc + 2 * e + d;          // sigma(k)
                g_M2f[t * 4 + r * 2 + h] =
                    __float2half(c2[(r2 * 16 + o2) * 16 + i2]);
            }
    }
    if (t < 256) {                        // M0f: (ks=0..7, lane)
        int ks = t >> 5;
        #pragma unroll
        for (int r = 0; r < 4; r++)
            #pragma unroll
            for (int h = 0; h < 2; h++) {
                int n = g + 8 * (r & 1);              // o0
                int k = 16 * ks + 8 * (r >> 1) + 2 * c + h;
                int i0 = k >> 3, r1 = k & 7;
                g_M0f[t * 8 + r * 2 + h] =
                    __float2half(c0[(n * 16 + i0) * 8 + r1]);
            }
    }
}

__device__ __forceinline__ void mma16816h(uint32_t* d, const uint32_t* a,
                                          uint32_t b0, uint32_t b1) {
    asm volatile(
        "mma.sync.aligned.m16n8k16.row.col.f16.f16.f16.f16 "
        "{%0,%1}, {%2,%3,%4,%5}, {%6,%7}, {%0,%1};\n"
        : "+r"(d[0]), "+r"(d[1])
        : "r"(a[0]), "r"(a[1]), "r"(a[2]), "r"(a[3]), "r"(b0), "r"(b1));
}

__device__ __forceinline__ void ldsm4(uint32_t* r, uint32_t addr) {
    asm volatile(
        "ldmatrix.sync.aligned.m8n8.x4.shared.b16 {%0,%1,%2,%3}, [%4];\n"
        : "=r"(r[0]), "=r"(r[1]), "=r"(r[2]), "=r"(r[3]) : "r"(addr));
}

__device__ __forceinline__ void stsm4(uint32_t addr, uint32_t r0, uint32_t r1,
                                      uint32_t r2, uint32_t r3) {
    asm volatile(
        "stmatrix.sync.aligned.m8n8.x4.shared.b16 [%0], {%1,%2,%3,%4};\n"
        :: "r"(addr), "r"(r0), "r"(r1), "r"(r2), "r"(r3) : "memory");
}

__device__ __forceinline__ uint32_t packh2(float lo, float hi) {
    __half2 h = __floats2half2_rn(lo, hi);
    return *(uint32_t*)&h;
}

__global__ void __launch_bounds__(256, 2)
tt_linear_kernel(const float* __restrict__ x, const float* __restrict__ bias,
                 float* __restrict__ y) {
    extern __shared__ __half smem[];
    uint32_t sbase;
    asm("{ .reg .u64 t; cvta.to.shared.u64 t, %1; cvt.u32.u64 %0, t; }"
        : "=r"(sbase) : "l"(smem));
    const uint32_t abase = (sbase + 1023) & ~1023u;
    char* scp = (char*)smem + (abase - sbase);
    float* Ysm = (float*)(scp + B_YS);    // separate region (no alias)

    const int b    = blockIdx.x;
    const int tid  = threadIdx.x;
    const int w    = tid >> 5;
    const int lane = tid & 31;
    const int g = lane >> 2, c = lane & 3;
    const int lsel = lane & 15;
    const int hi   = lane >> 4;
    const int msel = lane >> 3;            // stmatrix matrix id
    const int mrow = lane & 7;             // stmatrix row-in-matrix

    const int mw = w & 3;                  // stage B m-warp
    const int nw = w >> 2;                 // stage B n-warp

    const float* xr = x + (size_t)b * 4096;
    const uint4* M1v = (const uint4*)g_M1f;
    const uint2* M2v = (const uint2*)g_M2f;
    const uint4* M0v = (const uint4*)g_M0f;

    // =====================================================================
    // stage A: x (256x16 logical) @ M2^T -> BUF as T2.
    // warp w owns i0 in {2w, 2w+1} -> x loaded exactly once.
    // T2: row = i0*16 + o2 (256 rows x 256B), chunk = i1, XOR ^(row&7).
    // =====================================================================
    {
        uint32_t a[2][4];
        #pragma unroll
        for (int mi = 0; mi < 2; mi++) {
            const int li0 = 2 * w + mi;
            const float* rp = xr + li0 * 256 + 16 * g + 4 * c;
            float4 f0 = *(const float4*)(rp);
            float4 f1 = *(const float4*)(rp + 128);
            a[mi][0] = packh2(f0.x, f0.y);
            a[mi][1] = packh2(f1.x, f1.y);
            a[mi][2] = packh2(f0.z, f0.w);
            a[mi][3] = packh2(f1.z, f1.w);
        }
        const int i1s = mrow + 8 * (msel & 1);        // stsm source row
        const int li0s = 2 * w + (msel >> 1);
        #pragma unroll
        for (int nt8 = 0; nt8 < 16; nt8++) {         // o2
            uint2 bf = M2v[nt8 * 32 + lane];
            uint32_t d[2][2];
            #pragma unroll
            for (int mi = 0; mi < 2; mi++) {
                d[mi][0] = 0u; d[mi][1] = 0u;
                mma16816h(d[mi], a[mi], bf.x, bf.y);
            }
            const uint32_t swo = ((uint32_t)(i1s ^ (nt8 & 7))) << 4;
            stsm4(abase + (uint32_t)(16 * li0s + nt8) * 256 + swo,
                  d[0][0], d[0][1], d[1][0], d[1][1]);
        }
    }
    __syncthreads();

    // =====================================================================
    // stage B: T2 (256x128) @ M1^T, single pass, f16 acc (64 regs).
    // warp grid 4M x 2N: per warp 4 mi (64 m-rows), 4 jj (64 n-cols).
    // =====================================================================
    uint32_t accb[4][8][2];
    #pragma unroll
    for (int mi = 0; mi < 4; mi++)
        #pragma unroll
        for (int s = 0; s < 8; s++) {
            accb[mi][s][0] = 0u; accb[mi][s][1] = 0u;
        }
    {
        uint32_t abm[4];
        #pragma unroll
        for (int mi = 0; mi < 4; mi++) {
            const int ar = 64 * mw + 16 * mi + lsel;
            abm[mi] = abase + (uint32_t)ar * 256 +
                      ((uint32_t)(hi ^ (ar & 7)) << 4);
        }
        #pragma unroll
        for (int kk = 0; kk < 8; kk++) {
            uint32_t a[4][4];
            #pragma unroll
            for (int mi = 0; mi < 4; mi++)
                ldsm4(a[mi], abm[mi] ^ ((uint32_t)(2 * kk) << 4));
            #pragma unroll
            for (int jj = 0; jj < 4; jj++) {
                const int nt = 4 * nw + jj;           // 16-wide n-tile
                uint4 bf = M1v[(kk * 8 + nt) * 32 + lane];
                #pragma unroll
                for (int mi = 0; mi < 4; mi++) {
                    mma16816h(accb[mi][2 * jj],     a[mi], bf.x, bf.z);
                    mma16816h(accb[mi][2 * jj + 1], a[mi], bf.y, bf.w);
                }
            }
        }
    }
    __syncthreads();   // all T2 reads done; BUF reusable as T1

    // scatter to T1 (aliased): row = 16*o1 + o2 (256 rows x 256B),
    // chunk = i0, XOR ^(o2&7).
    {
        const int o2v = mrow + 8 * (msel & 1);
        #pragma unroll
        for (int p = 0; p < 2; p++) {
            const int c16 = 4 * mw + 2 * p + (msel >> 1);   // i0
            const uint32_t swo = ((uint32_t)(c16 ^ mrow)) << 4;
            #pragma unroll
            for (int slot = 0; slot < 8; slot++) {
                const int o1 = 8 * nw + slot;
                stsm4(abase + (uint32_t)(16 * o1 + o2v) * 256 + swo,
                      accb[2 * p][slot][0],     accb[2 * p][slot][1],
                      accb[2 * p + 1][slot][0], accb[2 * p + 1][slot][1]);
            }
        }
    }
    __syncthreads();

    // =====================================================================
    // stage C: T1 (256x128) @ M0^T -> f16 accumulators (8 regs), then
    // STS transpose straight into the SEPARATE Ysm region (no barrier).
    // =====================================================================
    uint32_t accc[2][2][2];
    #pragma unroll
    for (int mi = 0; mi < 2; mi++)
        #pragma unroll
        for (int nt = 0; nt < 2; nt++) {
            accc[mi][nt][0] = 0u; accc[mi][nt][1] = 0u;
        }
    #pragma unroll
    for (int ks = 0; ks < 8; ks++) {
        uint32_t a[2][4];
        #pragma unroll
        for (int mi = 0; mi < 2; mi++) {
            const int row = 16 * (w + 8 * mi) + lsel;
            ldsm4(a[mi], abase + (uint32_t)row * 256 +
                         ((uint32_t)((2 * ks + hi) ^ (lsel & 7)) << 4));
        }
        uint4 bf = M0v[ks * 32 + lane];
        #pragma unroll
        for (int mi = 0; mi < 2; mi++) {
            mma16816h(accc[mi][0], a[mi], bf.x, bf.z);
            mma16816h(accc[mi][1], a[mi], bf.y, bf.w);
        }
    }
    // transpose through Ysm (stride 260) — Ysm disjoint from BUF: no sync
    #pragma unroll
    for (int mi = 0; mi < 2; mi++) {
        const int row0 = 16 * (w + 8 * mi) + g;   // o1*16+o2
        #pragma unroll
        for (int nt = 0; nt < 2; nt++) {
            const int col0 = 8 * nt + 2 * c;      // o0
            float2 v0 = __half22float2(*(__half2*)&accc[mi][nt][0]);
            float2 v1 = __half22float2(*(__half2*)&accc[mi][nt][1]);
            Ysm[(col0)     * 260 + row0]     = v0.x;
            Ysm[(col0 + 1) * 260 + row0]     = v0.y;
            Ysm[(col0)     * 260 + row0 + 8] = v1.x;
            Ysm[(col0 + 1) * 260 + row0 + 8] = v1.y;
        }
    }
    __syncthreads();

    // ---- out: coalesced fp32 bias + store ----
    float* yr = y + (size_t)b * 4096;
    #pragma unroll
    for (int it = 0; it < 4; it++) {
        const int i = 4 * (tid + 256 * it);       // i = o0*256 + row
        const int o0 = i >> 8, row = i & 255;
        float4 v = *(const float4*)&Ysm[o0 * 260 + row];
        float4 bb = *(const float4*)&bias[i];
        v.x += bb.x; v.y += bb.y; v.z += bb.z; v.w += bb.w;
        *(float4*)&yr[i] = v;
    }
}

extern "C" void kernel_launch(void* const* d_in, const int* in_sizes, int n_in,
                              void* d_out, int out_size) {
    const float* x    = (const float*)d_in[0];
    const float* c0   = (const float*)d_in[1];
    const float* c1   = (const float*)d_in[2];
    const float* c2   = (const float*)d_in[3];
    const float* bias = (const float*)d_in[4];
    float* y = (float*)d_out;

    cudaFuncSetAttribute(tt_linear_kernel,
                         cudaFuncAttributeMaxDynamicSharedMemorySize,
                         SMEM_BYTES);

    tt_prep_cores<<<4, 512>>>(c0, c1, c2);
    tt_linear_kernel<<<8192, 256, SMEM_BYTES>>>(x, bias, y);
}